// round 15
// baseline (speedup 1.0000x reference)
#include <cuda_runtime.h>
#include <cuda_fp16.h>
#include <math.h>

#define SIMS 64
#define SD 65536            // 2^16 state dim
#define PI_F 3.14159265358979323846f
#define INV_SQRT2 0.70710678118654752440f
#define SCALE 16.0f         // amp scale to keep fp16 in normal range
#define INV_SC2 (1.0f / 256.0f)   // prob descale = 1/SCALE^2

// ---------------- device scratch (static, no allocation) ----------------
__device__ __align__(16) __half2 g_state[SIMS * SD];  // 16 MB (L2-resident)
__device__ float g_partial[SIMS][16][16];             // per-tile Z partials
__device__ unsigned g_ctr = 0;

__device__ __forceinline__ float wsum(float x) {
#pragma unroll
    for (int o = 16; o > 0; o >>= 1) x += __shfl_xor_sync(0xffffffffu, x, o);
    return x;
}

__device__ __forceinline__ void bf_regs(float2 a[16], int qb, float c, float s) {
#pragma unroll
    for (int p = 0; p < 8; p++) {
        const int j0 = ((p >> qb) << (qb + 1)) | (p & ((1 << qb) - 1));
        const int j1 = j0 | (1 << qb);
        const float r0 = c * a[j0].x - s * a[j1].x;
        const float r1 = s * a[j0].x + c * a[j1].x;
        const float i0 = c * a[j0].y - s * a[j1].y;
        const float i1 = s * a[j0].y + c * a[j1].y;
        a[j0].x = r0; a[j1].x = r1; a[j0].y = i0; a[j1].y = i1;
    }
}

__device__ __forceinline__ void bf_shfl(float2 a[16], const float* sc, const float* ss, int lane) {
#pragma unroll
    for (int q = 0; q < 5; q++) {
        const float c = sc[q], s = ss[q];
        const int m = 1 << q;
        const float sgn = (lane & m) ? s : -s;
#pragma unroll
        for (int j = 0; j < 16; j++) {
            const float ox = __shfl_xor_sync(0xffffffffu, a[j].x, m);
            const float oy = __shfl_xor_sync(0xffffffffu, a[j].y, m);
            a[j].x = fmaf(sgn, ox, c * a[j].x);
            a[j].y = fmaf(sgn, oy, c * a[j].y);
        }
    }
}

// ======================================================================
// K1: init product state * D0, RY_A on qubits 0..11 (R8 structure, prep fused,
//     all small-angle trig via MUFU __sincosf).
// Layout L1: t bits 0..7 <-> q0..7 (lane=0..4, warp=5..7), regs j <-> q8..11.
// Layout L1': lane <-> q0..4, warp w <-> q8..10, regs jp: bits0..2 <-> q5..7, bit3 <-> q11.
// ======================================================================
__global__ void __launch_bounds__(256) k_pass1(const float* __restrict__ x,
                                               const float* __restrict__ wcrz,
                                               const float* __restrict__ wry,
                                               const float* __restrict__ scale) {
    const int sim = blockIdx.x >> 4;
    const int tile = blockIdx.x & 15;
    const int t = threadIdx.x, lane = t & 31, w = t >> 5;
    __shared__ float2 sbuf[4096];
    __shared__ float2 A0s[512];          // CRZ L0, controls q0..7 (idx bits q0..8)
    __shared__ float2 sB0[2][16];        // CRZ L0, controls q8..15 ([q0][q8..11]); tile folded
    __shared__ float sc[12], ss[12], sTH[16];
    __shared__ float v0[16], v1[16], hw[32];

    if (t < 32) hw[t] = 0.5f * wcrz[t];
    if (t < 16) {
        const int q = t, bb = sim >> 3, p = sim & 7;
        const float xv = x[bb * 128 + (q >> 2) * 32 + p * 4 + (q & 3)];
        const float enc = tanhf(xv * scale[0]) * PI_F;
        float se, ce; __sincosf(enc * 0.5f, &se, &ce);
        v0[q] = (ce - se) * INV_SQRT2;
        v1[q] = (ce + se) * INV_SQRT2;
        if (q < 12) {
            float sA, cA; __sincosf((wry[q] + enc) * 0.5f, &sA, &cA);
            sc[q] = cA; ss[q] = sA;
        }
    }
    __syncthreads();
    if (t < 16) {   // TH over q8..15 (bits0..3 = q8..11 = t, tile = q12..15), SCALE folded
        float ph = SCALE;
#pragma unroll
        for (int q = 0; q < 4; q++) {
            ph *= ((t >> q) & 1) ? v1[8 + q] : v0[8 + q];
            ph *= ((tile >> q) & 1) ? v1[12 + q] : v0[12 + q];
        }
        sTH[t] = ph;
    }
    // A0 table: controls q0..7, target q+1 (idx bits 0..8 = q0..8)
    for (int i = t; i < 512; i += 256) {
        float a = 0.f;
#pragma unroll
        for (int q = 0; q < 8; q++)
            if ((i >> q) & 1) a += ((i >> (q + 1)) & 1) ? hw[q] : -hw[q];
        float s, c; __sincosf(a, &s, &c);
        A0s[i] = make_float2(c, s);
    }
    // B0 slice: controls q8..15, targets (q+1)&15; [q0][q8..11], tile = q12..15
    if (t < 32) {
        const int b0 = t >> 4, m = t & 15;
        const int i8 = m | (tile << 4);           // bits 0..7 = q8..15
        float a = 0.f;
#pragma unroll
        for (int q = 8; q < 16; q++) {
            if ((i8 >> (q - 8)) & 1) {
                const int tq = (q + 1) & 15;
                const int tb = (tq == 0) ? b0 : ((i8 >> (tq - 8)) & 1);
                a += tb ? hw[q] : -hw[q];
            }
        }
        float s, c; __sincosf(a, &s, &c);
        sB0[b0][m] = make_float2(c, s);
    }
    __syncthreads();

    // TL over q0..7 per thread
    float tl = 1.f;
#pragma unroll
    for (int q = 0; q < 8; q++) tl *= ((t >> q) & 1) ? v1[q] : v0[q];

    const float2 pa0 = A0s[t];
    const float2 pa1 = A0s[t | 256];
    const int myb0 = t & 1;
    float2 a[16];
#pragma unroll
    for (int j = 0; j < 16; j++) {
        const float2 pa = (j & 1) ? pa1 : pa0;       // A0 bit8 = q8 = j bit0
        const float2 pb = sB0[myb0][j];
        const float cr = pa.x * pb.x - pa.y * pb.y;
        const float ci = pa.x * pb.y + pa.y * pb.x;
        const float amp = tl * sTH[j];
        a[j] = make_float2(amp * cr, amp * ci);
    }
#pragma unroll
    for (int qb = 0; qb < 4; qb++) bf_regs(a, qb, sc[8 + qb], ss[8 + qb]);
    bf_shfl(a, sc, ss, lane);
#pragma unroll
    for (int j = 0; j < 16; j++) sbuf[(j << 8) | t] = a[j];
    __syncthreads();
    float2 b[16];
#pragma unroll
    for (int jp = 0; jp < 16; jp++) {
        const int oj = w | (jp & 8);
        const int ow = jp & 7;
        b[jp] = sbuf[(oj << 8) | (ow << 5) | lane];
    }
#pragma unroll
    for (int qb = 0; qb < 3; qb++) bf_regs(b, qb, sc[5 + qb], ss[5 + qb]);
    __half2* st = g_state + sim * SD + (tile << 12);
#pragma unroll
    for (int jp = 0; jp < 16; jp++)
        st[lane | ((jp & 7) << 5) | (w << 8) | ((jp & 8) << 8)] = __float22half2_rn(b[jp]);
}

// ======================================================================
// K2: RY_A(12..15), D1 (A1 per-thread + B1 smem), RY_B(12..15). Prep fused.
// ======================================================================
__global__ void __launch_bounds__(256) k_pass2(const float* __restrict__ x,
                                               const float* __restrict__ wcrz,
                                               const float* __restrict__ wry,
                                               const float* __restrict__ scale) {
    const int sim = blockIdx.x >> 4;
    const int blk = blockIdx.x & 15;
    const int t = threadIdx.x;
    const int low12 = (blk << 8) | t;
    __shared__ float2 sB1[64];           // [k][q0..1]
    __shared__ float scA[4], ssA[4], scB[4], ssB[4], sw1[16];
    if (t < 16) sw1[t] = 0.5f * wcrz[16 + t];
    if (t < 4) {
        const int q = 12 + t, bb = sim >> 3, p = sim & 7;
        const float xv = x[bb * 128 + 3 * 32 + p * 4 + t];
        const float enc = tanhf(xv * scale[0]) * PI_F;
        float sA, cA; __sincosf((wry[q] + enc) * 0.5f, &sA, &cA);
        scA[t] = cA; ssA[t] = sA;
        float sB, cB; __sincosf(wry[16 + q] * 0.5f, &sB, &cB);
        scB[t] = cB; ssB[t] = sB;
    }
    __syncthreads();
    // B1 slice: controls q8..15, targets (q+2)&15; idx bits 0..3=q8..11(blk),
    // 4..7=q12..15(k), 8..9=q0..1
    if (t < 64) {
        const int k = t >> 2, c2 = t & 3;
        const int i = blk | (k << 4) | (c2 << 8);
        float a = 0.f;
#pragma unroll
        for (int q = 8; q < 16; q++)
            if ((i >> (q - 8)) & 1) a += ((i >> (q - 6)) & 1) ? sw1[q] : -sw1[q];
        float s, c; __sincosf(a, &s, &c);
        sB1[t] = make_float2(c, s);
    }
    // A1 per thread: controls q0..7, target q+2 (bits 2..9)
    const int i10 = low12 & 1023;
    float aa = 0.f;
#pragma unroll
    for (int q = 0; q < 8; q++)
        if ((i10 >> q) & 1) aa += ((i10 >> (q + 2)) & 1) ? sw1[q] : -sw1[q];
    float pay, pax; __sincosf(aa, &pay, &pax);
    __syncthreads();

    __half2* st = g_state + sim * SD;
    float2 a[16];
#pragma unroll
    for (int k = 0; k < 16; k++) a[k] = __half22float2(st[(k << 12) | low12]);
#pragma unroll
    for (int qb = 0; qb < 4; qb++) bf_regs(a, qb, scA[qb], ssA[qb]);
    const int c2 = t & 3;
#pragma unroll
    for (int k = 0; k < 16; k++) {
        const float2 pb = sB1[(k << 2) | c2];
        const float cr = pax * pb.x - pay * pb.y;
        const float ci = pax * pb.y + pay * pb.x;
        const float nx = a[k].x * cr - a[k].y * ci;
        const float ny = a[k].x * ci + a[k].y * cr;
        a[k] = make_float2(nx, ny);
    }
#pragma unroll
    for (int qb = 0; qb < 4; qb++) bf_regs(a, qb, scB[qb], ssB[qb]);
#pragma unroll
    for (int k = 0; k < 16; k++) st[(k << 12) | low12] = __float22half2_rn(a[k]);
}

// ======================================================================
// K3: RY_B qubits 0..11 (R8 structure) + measurement + fused final output.
// ======================================================================
__global__ void __launch_bounds__(256) k_pass3(const float* __restrict__ wry,
                                               float* __restrict__ out) {
    const int sim = blockIdx.x >> 4;
    const int tile = blockIdx.x & 15;
    const int t = threadIdx.x, lane = t & 31, w = t >> 5;
    __shared__ float2 sbuf[4096];
    __shared__ float sc[12], ss[12];
    __shared__ float wred[8][13];
    __shared__ int sflag;
    if (t < 12) {
        float sB, cB; __sincosf(wry[16 + t] * 0.5f, &sB, &cB);
        sc[t] = cB; ss[t] = sB;
    }
    __syncthreads();
    // load in layout L1'
    const __half2* stg = g_state + sim * SD + (tile << 12);
    float2 b[16];
#pragma unroll
    for (int jp = 0; jp < 16; jp++)
        b[jp] = __half22float2(stg[lane | ((jp & 7) << 5) | (w << 8) | ((jp & 8) << 8)]);
    // RY_B q5..7 (jp bits 0..2) and q11 (jp bit 3)
#pragma unroll
    for (int qb = 0; qb < 3; qb++) bf_regs(b, qb, sc[5 + qb], ss[5 + qb]);
    bf_regs(b, 3, sc[11], ss[11]);
    bf_shfl(b, sc, ss, lane);                     // q0..4
    // transpose L1' -> L1
#pragma unroll
    for (int jp = 0; jp < 16; jp++)
        sbuf[lane | ((jp & 7) << 5) | (w << 8) | ((jp & 8) << 8)] = b[jp];
    __syncthreads();
    float2 a[16];
#pragma unroll
    for (int j = 0; j < 16; j++) a[j] = sbuf[(j << 8) | t];
#pragma unroll
    for (int qb = 0; qb < 3; qb++) bf_regs(a, qb, sc[8 + qb], ss[8 + qb]);   // q8..10

    // measurement (L1: t<->q0..7, j<->q8..11, tile<->q12..15)
    float pt = 0.f, z8 = 0.f, z9 = 0.f, z10 = 0.f, z11 = 0.f;
#pragma unroll
    for (int j = 0; j < 16; j++) {
        const float p = fmaf(a[j].y, a[j].y, a[j].x * a[j].x);
        pt += p;
        z8  += (j & 1) ? -p : p;
        z9  += (j & 2) ? -p : p;
        z10 += (j & 4) ? -p : p;
        z11 += (j & 8) ? -p : p;
    }
    float v[13];
#pragma unroll
    for (int q = 0; q < 8; q++) v[q] = ((t >> q) & 1) ? -pt : pt;
    v[8] = z8; v[9] = z9; v[10] = z10; v[11] = z11; v[12] = pt;
#pragma unroll
    for (int k = 0; k < 13; k++) v[k] = wsum(v[k]);
    if (lane == 0) {
#pragma unroll
        for (int k = 0; k < 13; k++) wred[w][k] = v[k];
    }
    __syncthreads();
    if (t < 16) {
        float s = 0.f;
        if (t < 12) {
#pragma unroll
            for (int w2 = 0; w2 < 8; w2++) s += wred[w2][t];
        } else {
            float tot = 0.f;
#pragma unroll
            for (int w2 = 0; w2 < 8; w2++) tot += wred[w2][12];
            s = ((tile >> (t - 12)) & 1) ? -tot : tot;
        }
        g_partial[sim][tile][t] = s;
    }
    // ---- last-block fused output ----
    __syncthreads();
    if (t == 0) {
        __threadfence();
        const unsigned old = atomicAdd(&g_ctr, 1u);
        sflag = (old == (unsigned)(SIMS * 16 - 1));
    }
    __syncthreads();
    if (!sflag) return;
    __threadfence();
    for (int it = t; it < SIMS * 16; it += 256) {
        const int sim2 = it >> 4, q = it & 15;
        float s = 0.f;
#pragma unroll
        for (int tl = 0; tl < 16; tl++) s += g_partial[sim2][tl][q];
        s *= INV_SC2;
        s = fminf(1.0f, fmaxf(-1.0f, s));
        const int bb = sim2 >> 3, p = sim2 & 7, h = q >> 2, ww = q & 3;
        out[bb * 128 + h * 32 + p * 4 + ww] = s;
    }
    if (t == 0) g_ctr = 0;    // reset for next graph replay
}

// ---------------- launch ----------------
extern "C" void kernel_launch(void* const* d_in, const int* in_sizes, int n_in,
                              void* d_out, int out_size) {
    const float* x     = (const float*)d_in[0];
    const float* wcrz  = (const float*)d_in[1];
    const float* wry   = (const float*)d_in[2];
    const float* scale = (const float*)d_in[3];
    float* out = (float*)d_out;

    k_pass1<<<SIMS * 16, 256>>>(x, wcrz, wry, scale);
    k_pass2<<<SIMS * 16, 256>>>(x, wcrz, wry, scale);
    k_pass3<<<SIMS * 16, 256>>>(wry, out);
}

// round 16
// speedup vs baseline: 1.1644x; 1.1644x over previous
#include <cuda_runtime.h>
#include <math.h>

#define SIMS 64
#define SD 65536            // 2^16 state dim
#define PI_F 3.14159265358979323846f
#define INV_SQRT2 0.70710678118654752440f

// ---------------- device scratch (static, no allocation) ----------------
__device__ __align__(16) float2 g_state[SIMS * SD];   // 32 MB (L2-resident)
__device__ float2 g_A0[512];    // CRZ layer0, controls q0..7  (idx bits 0..8 = qubit bits 0..8)
__device__ float2 g_B0[512];    // CRZ layer0, controls q8..15 (idx bits 0..7 = q8..15, bit 8 = q0)
__device__ float2 g_A1[1024];   // CRZ layer1, controls q0..7  (idx bits 0..9 = qubit bits 0..9)
__device__ float2 g_B1[1024];   // CRZ layer1, controls q8..15 (idx bits 0..7 = q8..15, bits 8..9 = q0..1)
__device__ float g_TL[SIMS][256];                     // product tables (qubits 0..7)
__device__ float g_TH[SIMS][256];                     // product tables (qubits 8..15)
__device__ float g_cA[SIMS][16], g_sA[SIMS][16];      // cos/sin((w_ry0+enc)/2)
__device__ float g_cB[16], g_sB[16];                  // cos/sin(w_ry1/2)
__device__ float g_partial[SIMS][16][16];             // per-tile Z partials
__device__ unsigned g_ctr = 0;

// ---------------- prep: per-sim params + split CRZ phase tables ----------------
__global__ void k_prep(const float* __restrict__ x,
                       const float* __restrict__ wcrz,
                       const float* __restrict__ wry,
                       const float* __restrict__ scale) {
    const int blk = blockIdx.x;
    const int t = threadIdx.x;         // 256 threads
    if (blk < SIMS) {
        const int sim = blk;
        __shared__ float v0[16], v1[16];
        if (t < 16) {
            const int q = t;
            const int bb = sim >> 3, p = sim & 7;
            const float xv = x[bb * 128 + (q >> 2) * 32 + p * 4 + (q & 3)];
            const float enc = tanhf(xv * scale[0]) * PI_F;
            float se, ce;
            __sincosf(enc * 0.5f, &se, &ce);
            v0[q] = (ce - se) * INV_SQRT2;
            v1[q] = (ce + se) * INV_SQRT2;
            float sA, cA;
            __sincosf((wry[q] + enc) * 0.5f, &sA, &cA);   // merged RY(w_ry0 + enc)
            g_cA[sim][q] = cA;  g_sA[sim][q] = sA;
            if (sim == 0) {
                float sB, cB;
                __sincosf(wry[16 + q] * 0.5f, &sB, &cB);
                g_cB[q] = cB;  g_sB[q] = sB;
            }
        }
        __syncthreads();
        const int m = t;
        float pl = 1.0f, ph = 1.0f;
#pragma unroll
        for (int q = 0; q < 8; q++) {
            pl *= ((m >> q) & 1) ? v1[q] : v0[q];
            ph *= ((m >> q) & 1) ? v1[8 + q] : v0[8 + q];
        }
        g_TL[sim][m] = pl;
        g_TH[sim][m] = ph;
    } else {
        // table builder blocks: blk = 64..67
        __shared__ float w[32];
        if (t < 32) w[t] = 0.5f * wcrz[t];
        __syncthreads();
        const int which = blk - SIMS;
        if (which == 0) {          // A0: controls q0..7, targets q+1 (bits 1..8)
            for (int i = t; i < 512; i += 256) {
                float a = 0.0f;
#pragma unroll
                for (int q = 0; q < 8; q++)
                    if ((i >> q) & 1) a += ((i >> (q + 1)) & 1) ? w[q] : -w[q];
                float s, c; __sincosf(a, &s, &c);
                g_A0[i] = make_float2(c, s);
            }
        } else if (which == 1) {   // B0: controls q8..15, targets q+1 mod 16
            for (int i = t; i < 512; i += 256) {
                float a = 0.0f;
#pragma unroll
                for (int q = 8; q < 16; q++) {
                    if ((i >> (q - 8)) & 1) {
                        const int tq = (q + 1) & 15;
                        const int tb = (tq == 0) ? ((i >> 8) & 1) : ((i >> (tq - 8)) & 1);
                        a += tb ? w[q] : -w[q];
                    }
                }
                float s, c; __sincosf(a, &s, &c);
                g_B0[i] = make_float2(c, s);
            }
        } else if (which == 2) {   // A1: controls q0..7, targets q+2 (bits 2..9)
            for (int i = t; i < 1024; i += 256) {
                float a = 0.0f;
#pragma unroll
                for (int q = 0; q < 8; q++)
                    if ((i >> q) & 1) a += ((i >> (q + 2)) & 1) ? w[16 + q] : -w[16 + q];
                float s, c; __sincosf(a, &s, &c);
                g_A1[i] = make_float2(c, s);
            }
        } else {                   // B1: controls q8..15, targets q+2 mod 16
            for (int i = t; i < 1024; i += 256) {
                float a = 0.0f;
#pragma unroll
                for (int q = 8; q < 16; q++) {
                    if ((i >> (q - 8)) & 1) {
                        const int tq = (q + 2) & 15;
                        const int tb = (tq >= 8) ? ((i >> (tq - 8)) & 1) : ((i >> (8 + tq)) & 1);
                        a += tb ? w[16 + q] : -w[16 + q];
                    }
                }
                float s, c; __sincosf(a, &s, &c);
                g_B1[i] = make_float2(c, s);
            }
        }
    }
}

// ---------------- butterfly helpers ----------------
__device__ __forceinline__ void bf_regs(float2 a[16], int qb, float c, float s) {
#pragma unroll
    for (int p = 0; p < 8; p++) {
        const int j0 = ((p >> qb) << (qb + 1)) | (p & ((1 << qb) - 1));
        const int j1 = j0 | (1 << qb);
        const float r0 = c * a[j0].x - s * a[j1].x;
        const float r1 = s * a[j0].x + c * a[j1].x;
        const float i0 = c * a[j0].y - s * a[j1].y;
        const float i1 = s * a[j0].y + c * a[j1].y;
        a[j0].x = r0; a[j1].x = r1; a[j0].y = i0; a[j1].y = i1;
    }
}

__device__ __forceinline__ void bf_shfl(float2 a[16], const float* sc, const float* ss, int lane) {
#pragma unroll
    for (int q = 0; q < 5; q++) {
        const float c = sc[q], s = ss[q];
        const int m = 1 << q;
        const float sgn = (lane & m) ? s : -s;
#pragma unroll
        for (int j = 0; j < 16; j++) {
            const float ox = __shfl_xor_sync(0xffffffffu, a[j].x, m);
            const float oy = __shfl_xor_sync(0xffffffffu, a[j].y, m);
            a[j].x = fmaf(sgn, ox, c * a[j].x);
            a[j].y = fmaf(sgn, oy, c * a[j].y);
        }
    }
}

// ---------------- K1: init * D0 (split tables), RY_A on qubits 0..11 ----------------
// Layout L1: t bits 0..7 <-> qubits 0..7 (lane=0..4, warp=5..7), regs j <-> qubits 8..11.
// Layout L1': lane <-> 0..4, warp w <-> 8..10, regs jp: bits0..2 <-> 5..7, bit3 <-> 11.
__global__ void __launch_bounds__(256) k_pass1() {
    const int sim = blockIdx.x >> 4;
    const int tile = blockIdx.x & 15;
    const int t = threadIdx.x;
    const int lane = t & 31;
    const int w = t >> 5;
    __shared__ float2 sbuf[4096];
    __shared__ float sc[16], ss[16], sTH[16];
    __shared__ float2 sB0[2][16];
    if (t < 16) {
        sc[t] = g_cA[sim][t];
        ss[t] = g_sA[sim][t];
        sTH[t] = g_TH[sim][(tile << 4) | t];
    }
    if (t < 32) {
        const int b0 = t >> 4, j = t & 15;
        sB0[b0][j] = g_B0[(tile << 4) | j | (b0 << 8)];
    }
    __syncthreads();
    const float tl = g_TL[sim][t];
    const float2 pa0 = g_A0[t];
    const float2 pa1 = g_A0[t | 256];
    const int myb0 = t & 1;
    float2 a[16];
#pragma unroll
    for (int j = 0; j < 16; j++) {
        const float2 pa = (j & 1) ? pa1 : pa0;       // A0 bit8 = qubit8 = j bit0
        const float2 pb = sB0[myb0][j];
        const float cr = pa.x * pb.x - pa.y * pb.y;  // e^{i(A0+B0)}
        const float ci = pa.x * pb.y + pa.y * pb.x;
        const float amp = tl * sTH[j];
        a[j] = make_float2(amp * cr, amp * ci);
    }
#pragma unroll
    for (int qb = 0; qb < 4; qb++) bf_regs(a, qb, sc[8 + qb], ss[8 + qb]);
    bf_shfl(a, sc, ss, lane);
#pragma unroll
    for (int j = 0; j < 16; j++) sbuf[(j << 8) | t] = a[j];
    __syncthreads();
    float2 b[16];
#pragma unroll
    for (int jp = 0; jp < 16; jp++) {
        const int oj = w | (jp & 8);
        const int ow = jp & 7;
        b[jp] = sbuf[(oj << 8) | (ow << 5) | lane];
    }
#pragma unroll
    for (int qb = 0; qb < 3; qb++) bf_regs(b, qb, sc[5 + qb], ss[5 + qb]);
    float2* st = g_state + sim * SD + (tile << 12);
#pragma unroll
    for (int jp = 0; jp < 16; jp++)
        st[lane | ((jp & 7) << 5) | (w << 8) | ((jp & 8) << 8)] = b[jp];
}

// ---------------- K2: RY_A(12..15), D1 (split tables), RY_B(12..15) ----------------
__global__ void __launch_bounds__(256) k_pass2() {
    const int sim = blockIdx.x >> 4;
    const int blk = blockIdx.x & 15;
    const int t = threadIdx.x;
    const int low12 = (blk << 8) | t;
    __shared__ float2 sB1[64];           // [k][q0..1]
    __shared__ float scA[4], ssA[4], scB[4], ssB[4];
    if (t < 64) {
        const int k = t >> 2, c2 = t & 3;
        sB1[t] = g_B1[blk | (k << 4) | (c2 << 8)];
    }
    if (t < 4) {
        scA[t] = g_cA[sim][12 + t]; ssA[t] = g_sA[sim][12 + t];
        scB[t] = g_cB[12 + t];      ssB[t] = g_sB[12 + t];
    }
    __syncthreads();
    const float2 pa = g_A1[low12 & 1023];
    float2* st = g_state + sim * SD;
    float2 a[16];
#pragma unroll
    for (int k = 0; k < 16; k++) a[k] = st[(k << 12) | low12];
#pragma unroll
    for (int qb = 0; qb < 4; qb++) bf_regs(a, qb, scA[qb], ssA[qb]);
    const int c2 = t & 3;
#pragma unroll
    for (int k = 0; k < 16; k++) {
        const float2 pb = sB1[(k << 2) | c2];
        const float cr = pa.x * pb.x - pa.y * pb.y;
        const float ci = pa.x * pb.y + pa.y * pb.x;
        const float nx = a[k].x * cr - a[k].y * ci;
        const float ny = a[k].x * ci + a[k].y * cr;
        a[k] = make_float2(nx, ny);
    }
#pragma unroll
    for (int qb = 0; qb < 4; qb++) bf_regs(a, qb, scB[qb], ssB[qb]);
#pragma unroll
    for (int k = 0; k < 16; k++) st[(k << 12) | low12] = a[k];
}

// ---------------- K3: RY_B qubits 0..11 + measurement + fused final output ----------------
__global__ void __launch_bounds__(256) k_pass3(float* __restrict__ out) {
    const int sim = blockIdx.x >> 4;
    const int tile = blockIdx.x & 15;
    const int t = threadIdx.x;
    const int lane = t & 31;
    const int w = t >> 5;
    __shared__ float2 sbuf[4096];
    __shared__ float sc[16], ss[16];
    __shared__ float wred[8][13];
    __shared__ int sflag;
    if (t < 16) { sc[t] = g_cB[t]; ss[t] = g_sB[t]; }
    __syncthreads();
    // load in layout L1' (lane<->0..4, w<->8..10, jp bits0..2<->5..7, bit3<->11)
    const float2* stg = g_state + sim * SD + (tile << 12);
    float2 b[16];
#pragma unroll
    for (int jp = 0; jp < 16; jp++)
        b[jp] = stg[lane | ((jp & 7) << 5) | (w << 8) | ((jp & 8) << 8)];
    // RY_B qubits 5..7 (jp bits 0..2) and 11 (jp bit 3)
#pragma unroll
    for (int qb = 0; qb < 3; qb++) bf_regs(b, qb, sc[5 + qb], ss[5 + qb]);
    bf_regs(b, 3, sc[11], ss[11]);
    // RY_B qubits 0..4 (shfl)
    bf_shfl(b, sc, ss, lane);
    // transpose L1' -> L1
#pragma unroll
    for (int jp = 0; jp < 16; jp++)
        sbuf[lane | ((jp & 7) << 5) | (w << 8) | ((jp & 8) << 8)] = b[jp];
    __syncthreads();
    float2 a[16];
#pragma unroll
    for (int j = 0; j < 16; j++) a[j] = sbuf[(j << 8) | t];
    // RY_B qubits 8..10 (j bits 0..2; q11 already done)
#pragma unroll
    for (int qb = 0; qb < 3; qb++) bf_regs(a, qb, sc[8 + qb], ss[8 + qb]);

    // measurement (layout L1: t<->q0..7, j<->q8..11, tile<->q12..15)
    float ptot = 0.0f, z8 = 0.0f, z9 = 0.0f, z10 = 0.0f, z11 = 0.0f;
#pragma unroll
    for (int j = 0; j < 16; j++) {
        const float p = fmaf(a[j].y, a[j].y, a[j].x * a[j].x);
        ptot += p;
        z8  += (j & 1) ? -p : p;
        z9  += (j & 2) ? -p : p;
        z10 += (j & 4) ? -p : p;
        z11 += (j & 8) ? -p : p;
    }
    float v[13];
#pragma unroll
    for (int q = 0; q < 8; q++) v[q] = ((t >> q) & 1) ? -ptot : ptot;
    v[8] = z8; v[9] = z9; v[10] = z10; v[11] = z11; v[12] = ptot;
#pragma unroll
    for (int k = 0; k < 13; k++) {
        float xv = v[k];
#pragma unroll
        for (int o = 16; o > 0; o >>= 1) xv += __shfl_xor_sync(0xffffffffu, xv, o);
        v[k] = xv;
    }
    if (lane == 0) {
#pragma unroll
        for (int k = 0; k < 13; k++) wred[w][k] = v[k];
    }
    __syncthreads();
    if (t < 16) {
        float s = 0.0f;
        if (t < 12) {
#pragma unroll
            for (int w2 = 0; w2 < 8; w2++) s += wred[w2][t];
        } else {
            float tot = 0.0f;
#pragma unroll
            for (int w2 = 0; w2 < 8; w2++) tot += wred[w2][12];
            s = ((tile >> (t - 12)) & 1) ? -tot : tot;
        }
        g_partial[sim][tile][t] = s;
    }
    // ---- last-block fused output (deterministic fixed-order sums) ----
    __syncthreads();
    if (t == 0) {
        __threadfence();
        const unsigned old = atomicAdd(&g_ctr, 1u);
        sflag = (old == (unsigned)(SIMS * 16 - 1));
    }
    __syncthreads();
    if (!sflag) return;
    __threadfence();
    for (int it = t; it < SIMS * 16; it += 256) {
        const int sim2 = it >> 4, q = it & 15;
        float s = 0.0f;
#pragma unroll
        for (int tl = 0; tl < 16; tl++) s += g_partial[sim2][tl][q];
        s = fminf(1.0f, fmaxf(-1.0f, s));
        const int bb = sim2 >> 3, p = sim2 & 7, h = q >> 2, ww = q & 3;
        out[bb * 128 + h * 32 + p * 4 + ww] = s;
    }
    if (t == 0) g_ctr = 0;    // reset for next graph replay
}

// ---------------- launch ----------------
extern "C" void kernel_launch(void* const* d_in, const int* in_sizes, int n_in,
                              void* d_out, int out_size) {
    const float* x     = (const float*)d_in[0];
    const float* wcrz  = (const float*)d_in[1];
    const float* wry   = (const float*)d_in[2];
    const float* scale = (const float*)d_in[3];
    float* out = (float*)d_out;

    k_prep<<<SIMS + 4, 256>>>(x, wcrz, wry, scale);
    k_pass1<<<SIMS * 16, 256>>>();
    k_pass2<<<SIMS * 16, 256>>>();
    k_pass3<<<SIMS * 16, 256>>>(out);
}